// round 2
// baseline (speedup 1.0000x reference)
#include <cuda_runtime.h>

#define D    768
#define NH   12
#define DKH  64
#define TT   16
#define ENCL 256
#define DFF  3072
#define NV   32128
#define NL   4
#define NB   2
#define EPSF 1e-6f
#define KS   8
#define KLEN (D/KS)   // 96
#define RSQRT_D 0.03608439182435161f   // 768^-0.5

// ------------------------------------------------------------------ scratch
__device__ float g_x  [NB*D];
__device__ float g_xf [NB*D];
__device__ float g_q  [NB*D];
__device__ float g_att[NB*D];
__device__ float g_ff [NB*DFF];
__device__ float g_kc [NL*NB*TT*D];             // self-attn K cache [l][b][t][d]
__device__ float g_vc [NL*NB*TT*D];             // self-attn V cache
__device__ float g_ckt[NL*NB*NH*DKH*ENCL];      // cross K, transposed per head [l][b][h][dk][pos]
__device__ float g_cv [NL*NB*ENCL*D];           // cross V, natural layout
__device__ int   g_tok[NB*TT];

// ------------------------------------------------------------------ helpers
__device__ __forceinline__ void rms_inv2(float* inv, float* sred) {
    float s0 = 0.f, s1 = 0.f;
    for (int i = threadIdx.x; i < D; i += 256) {
        float a = g_x[i], b = g_x[D + i];
        s0 += a * a; s1 += b * b;
    }
    #pragma unroll
    for (int o = 16; o; o >>= 1) {
        s0 += __shfl_xor_sync(0xffffffffu, s0, o);
        s1 += __shfl_xor_sync(0xffffffffu, s1, o);
    }
    if ((threadIdx.x & 31) == 0) {
        sred[threadIdx.x >> 5]     = s0;
        sred[8 + (threadIdx.x >> 5)] = s1;
    }
    __syncthreads();
    if (threadIdx.x == 0) {
        float t0 = 0.f, t1 = 0.f;
        #pragma unroll
        for (int w = 0; w < 8; w++) { t0 += sred[w]; t1 += sred[8 + w]; }
        sred[16] = rsqrtf(t0 / (float)D + EPSF);
        sred[17] = rsqrtf(t1 / (float)D + EPSF);
    }
    __syncthreads();
    inv[0] = sred[16]; inv[1] = sred[17];
}

// ------------------------------------------------------------------ kernels
__global__ void k_init() { g_tok[0] = 0; g_tok[TT] = 0; }

__global__ void k_embed(const float* __restrict__ emb, int t) {
    int b = blockIdx.x, d = threadIdx.x;           // 768 threads
    int tok = g_tok[b * TT + t];
    g_x[b * D + d] = emb[(size_t)tok * D + d];
}

// mode 0: zero g_q + K/V cache slot (l,t); mode 1: zero g_q + g_ff
__global__ void k_zero(int mode, int l, int t) {
    int idx = blockIdx.x * 256 + threadIdx.x;
    if (mode == 0) {
        if (idx < NB * D) g_q[idx] = 0.f;
        else if (idx < 2 * NB * D) {
            int j = idx - NB * D; int b = j / D, d = j % D;
            g_kc[((size_t)(l * NB + b) * TT + t) * D + d] = 0.f;
        } else if (idx < 3 * NB * D) {
            int j = idx - 2 * NB * D; int b = j / D, d = j % D;
            g_vc[((size_t)(l * NB + b) * TT + t) * D + d] = 0.f;
        }
    } else {
        if (idx < NB * D) g_q[idx] = 0.f;
        else if (idx < NB * D + NB * DFF) g_ff[idx - NB * D] = 0.f;
    }
}

// fused rmsnorm + GEMV (inner dim = D), ksplit partials via atomicAdd
// outsel: 0 -> g_q, 1 -> K cache slot, 2 -> V cache slot, 3 -> g_ff
__global__ __launch_bounds__(256) void k_ln_gemv(
    const float* __restrict__ lnw, const float* __restrict__ W,
    int DOUT, int ostride, int outsel, int l, int t)
{
    __shared__ float sred[18];
    __shared__ float sh0[KLEN], sh1[KLEN];
    int c  = blockIdx.x / KS;
    int ks = blockIdx.x % KS;
    float inv[2];
    rms_inv2(inv, sred);
    int i0 = ks * KLEN;
    if (threadIdx.x < KLEN) {
        int i = threadIdx.x;
        float w = lnw[i0 + i];
        sh0[i] = g_x[i0 + i]     * inv[0] * w;
        sh1[i] = g_x[D + i0 + i] * inv[1] * w;
    }
    __syncthreads();
    int col = (c << 8) + threadIdx.x;
    const float* Wp = W + (size_t)i0 * DOUT + col;
    float a0 = 0.f, a1 = 0.f;
    #pragma unroll 8
    for (int i = 0; i < KLEN; i++) {
        float w = Wp[(size_t)i * DOUT];
        a0 += sh0[i] * w; a1 += sh1[i] * w;
    }
    float* o;
    if      (outsel == 0) o = g_q;
    else if (outsel == 1) o = g_kc + ((size_t)(l * NB) * TT + t) * D;
    else if (outsel == 2) o = g_vc + ((size_t)(l * NB) * TT + t) * D;
    else                  o = g_ff;
    atomicAdd(o + col, a0);
    atomicAdd(o + ostride + col, a1);
}

// GEMV with residual accumulate into g_x. insel 0: in=g_att; 1: in=relu(g_ff)
__global__ __launch_bounds__(256) void k_gemv_res(
    const float* __restrict__ W, int DIN, int klen, int insel)
{
    __shared__ float sh0[192], sh1[192];
    int nks = DIN / klen;
    int c  = blockIdx.x / nks;
    int ks = blockIdx.x % nks;
    int i0 = ks * klen;
    for (int i = threadIdx.x; i < klen; i += 256) {
        float a, b;
        if (insel == 0) { a = g_att[i0 + i];            b = g_att[D + i0 + i]; }
        else            { a = fmaxf(g_ff[i0 + i], 0.f); b = fmaxf(g_ff[DFF + i0 + i], 0.f); }
        sh0[i] = a; sh1[i] = b;
    }
    __syncthreads();
    int col = (c << 8) + threadIdx.x;
    const float* Wp = W + (size_t)i0 * D + col;
    float a0 = 0.f, a1 = 0.f;
    #pragma unroll 8
    for (int i = 0; i < klen; i++) {
        float w = Wp[(size_t)i * D];
        a0 += sh0[i] * w; a1 += sh1[i] * w;
    }
    atomicAdd(g_x + col, a0);
    atomicAdd(g_x + D + col, a1);
}

// self attention at position t over cached keys 0..t (24 blocks, 64 thr)
__global__ void k_self_attn(const float* __restrict__ rel_bias, int l, int t) {
    int b = blockIdx.x / NH, h = blockIdx.x % NH;
    int tid = threadIdx.x;
    __shared__ float sq[DKH];
    __shared__ float sp[TT];
    __shared__ float se[TT];
    sq[tid] = g_q[b * D + h * DKH + tid];
    __syncthreads();
    int n = t + 1;
    if (tid < n) {
        const float* kp = g_kc + ((size_t)(l * NB + b) * TT + tid) * D + h * DKH;
        float s = 0.f;
        #pragma unroll
        for (int d = 0; d < DKH; d++) s += sq[d] * kp[d];
        // rel distance t-tid < 16 = max_exact -> bucket == distance
        sp[tid] = s + rel_bias[(t - tid) * NH + h];
    }
    __syncthreads();
    float mx = -1e30f;
    for (int j = 0; j < n; j++) mx = fmaxf(mx, sp[j]);
    if (tid < n) se[tid] = expf(sp[tid] - mx);
    __syncthreads();
    float sum = 0.f;
    for (int j = 0; j < n; j++) sum += se[j];
    float o = 0.f;
    for (int j = 0; j < n; j++)
        o += se[j] * g_vc[((size_t)(l * NB + b) * TT + j) * D + h * DKH + tid];
    g_att[b * D + h * DKH + tid] = o / sum;
}

// cross attention over 256 encoder positions (24 blocks, 256 thr)
__global__ __launch_bounds__(256) void k_cross_attn(int l) {
    int b = blockIdx.x / NH, h = blockIdx.x % NH;
    int tid = threadIdx.x;
    __shared__ float sq[DKH];
    __shared__ float se[ENCL];
    __shared__ float red[8];
    __shared__ float sMS[2];
    __shared__ float so[4][DKH];
    if (tid < DKH) sq[tid] = g_q[b * D + h * DKH + tid];
    __syncthreads();
    const float* kt = g_ckt + ((size_t)((l * NB + b) * NH + h) * DKH) * ENCL;
    float s = 0.f;
    #pragma unroll 16
    for (int d = 0; d < DKH; d++) s += sq[d] * kt[(size_t)d * ENCL + tid];
    float m = s;
    for (int o = 16; o; o >>= 1) m = fmaxf(m, __shfl_xor_sync(0xffffffffu, m, o));
    if ((tid & 31) == 0) red[tid >> 5] = m;
    __syncthreads();
    if (tid == 0) {
        float mm = red[0];
        for (int w = 1; w < 8; w++) mm = fmaxf(mm, red[w]);
        sMS[0] = mm;
    }
    __syncthreads();
    float e = expf(s - sMS[0]);
    se[tid] = e;
    float ss = e;
    for (int o = 16; o; o >>= 1) ss += __shfl_xor_sync(0xffffffffu, ss, o);
    if ((tid & 31) == 0) red[tid >> 5] = ss;
    __syncthreads();
    if (tid == 0) {
        float t2 = 0.f;
        for (int w = 0; w < 8; w++) t2 += red[w];
        sMS[1] = t2;
    }
    __syncthreads();
    int g = tid >> 6, d = tid & 63;
    const float* vp = g_cv + (size_t)((l * NB + b) * ENCL) * D + h * DKH + d;
    float acc = 0.f;
    for (int j = g * 64; j < g * 64 + 64; j++) acc += se[j] * vp[(size_t)j * D];
    so[g][d] = acc;
    __syncthreads();
    if (tid < DKH)
        g_att[b * D + h * DKH + tid] =
            (so[0][tid] + so[1][tid] + so[2][tid] + so[3][tid]) / sMS[1];
}

__global__ void k_final_rms(const float* __restrict__ lnw) {
    __shared__ float sred[18];
    float inv[2];
    rms_inv2(inv, sred);
    for (int i = threadIdx.x; i < D; i += 256) {
        float w = lnw[i] * RSQRT_D;
        g_xf[i]     = g_x[i]     * inv[0] * w;
        g_xf[D + i] = g_x[D + i] * inv[1] * w;
    }
}

// logits over vocab: one warp per vocab row, both batches per warp
__global__ __launch_bounds__(256) void k_logits(
    const float* __restrict__ emb, float* __restrict__ out, int t)
{
    __shared__ float sx0[D], sx1[D];
    for (int i = threadIdx.x; i < D; i += 256) { sx0[i] = g_xf[i]; sx1[i] = g_xf[D + i]; }
    __syncthreads();
    int warp = threadIdx.x >> 5, lane = threadIdx.x & 31;
    int v = blockIdx.x * 8 + warp;
    if (v >= NV) return;
    const float4* e = (const float4*)(emb + (size_t)v * D);
    float a0 = 0.f, a1 = 0.f;
    #pragma unroll
    for (int i = lane; i < D / 4; i += 32) {
        float4 w = e[i];
        a0 += w.x * sx0[4*i] + w.y * sx0[4*i+1] + w.z * sx0[4*i+2] + w.w * sx0[4*i+3];
        a1 += w.x * sx1[4*i] + w.y * sx1[4*i+1] + w.z * sx1[4*i+2] + w.w * sx1[4*i+3];
    }
    for (int o = 16; o; o >>= 1) {
        a0 += __shfl_xor_sync(0xffffffffu, a0, o);
        a1 += __shfl_xor_sync(0xffffffffu, a1, o);
    }
    if (lane == 0) {
        out[((size_t)0 * TT + t) * NV + v] = a0;
        out[((size_t)1 * TT + t) * NV + v] = a1;
    }
}

__global__ void k_argmax(const float* __restrict__ out, int t) {
    int b = blockIdx.x;
    const float* lg = out + ((size_t)b * TT + t) * NV;
    float bv = -1e30f; int bi = 0;
    for (int v = threadIdx.x; v < NV; v += 256) {
        float x = lg[v];
        if (x > bv) { bv = x; bi = v; }
    }
    __shared__ float sv[256]; __shared__ int si[256];
    sv[threadIdx.x] = bv; si[threadIdx.x] = bi;
    __syncthreads();
    for (int s = 128; s; s >>= 1) {
        if (threadIdx.x < s) {
            float ov = sv[threadIdx.x + s]; int oi = si[threadIdx.x + s];
            if (ov > sv[threadIdx.x] ||
                (ov == sv[threadIdx.x] && oi < si[threadIdx.x])) {
                sv[threadIdx.x] = ov; si[threadIdx.x] = oi;
            }
        }
        __syncthreads();
    }
    if (threadIdx.x == 0) g_tok[b * TT + t + 1] = si[0];
}

// precompute cross K (transposed per head) and V for all layers
__global__ __launch_bounds__(256) void k_cross_kv(
    const float* __restrict__ enc, const float* __restrict__ ckw,
    const float* __restrict__ cvw)
{
    __shared__ float sx[8][D];                // 24KB
    int bx = blockIdx.x;
    int c   = bx % 3; bx /= 3;
    int rb  = bx % 64; bx /= 64;
    int mat = bx % 2;
    int l   = bx / 2;
    int row0 = rb * 8;                        // rows over B*ENC = 512
    for (int i = threadIdx.x; i < 8 * D; i += 256)
        sx[i / D][i % D] = enc[(size_t)row0 * D + i];
    __syncthreads();
    const float* W = (mat == 0 ? ckw : cvw) + (size_t)l * D * D;
    int col = c * 256 + threadIdx.x;
    float acc[8];
    #pragma unroll
    for (int r = 0; r < 8; r++) acc[r] = 0.f;
    const float* Wp = W + col;
    #pragma unroll 4
    for (int i = 0; i < D; i++) {
        float w = Wp[(size_t)i * D];
        #pragma unroll
        for (int r = 0; r < 8; r++) acc[r] += sx[r][i] * w;
    }
    int h = col / DKH, dd = col % DKH;
    for (int r = 0; r < 8; r++) {
        int g = row0 + r; int b = g / ENCL; int p = g % ENCL;
        if (mat == 0)
            g_ckt[(((size_t)(l * NB + b) * NH + h) * DKH + dd) * ENCL + p] = acc[r];
        else
            g_cv[((size_t)(l * NB + b) * ENCL + p) * D + col] = acc[r];
    }
}

// ------------------------------------------------------------------ launch
extern "C" void kernel_launch(void* const* d_in, const int* in_sizes, int n_in,
                              void* d_out, int out_size) {
    const float* enc = (const float*)d_in[0];
    const float* emb = (const float*)d_in[1];
    const float* ln1 = (const float*)d_in[2];
    const float* qw  = (const float*)d_in[3];
    const float* kw  = (const float*)d_in[4];
    const float* vw  = (const float*)d_in[5];
    const float* ow  = (const float*)d_in[6];
    const float* ln2 = (const float*)d_in[7];
    const float* cqw = (const float*)d_in[8];
    const float* ckw = (const float*)d_in[9];
    const float* cvw = (const float*)d_in[10];
    const float* cow = (const float*)d_in[11];
    const float* ln3 = (const float*)d_in[12];
    const float* wi  = (const float*)d_in[13];
    const float* wo  = (const float*)d_in[14];
    const float* fln = (const float*)d_in[15];
    const float* rb  = (const float*)d_in[16];
    float* out = (float*)d_out;

    k_cross_kv<<<1536, 256>>>(enc, ckw, cvw);
    k_init<<<1, 1>>>();

    for (int t = 0; t < TT; t++) {
        k_embed<<<NB, 768>>>(emb, t);
        for (int l = 0; l < NL; l++) {
            size_t MO = (size_t)l * D * D;
            k_zero<<<18, 256>>>(0, l, t);
            k_ln_gemv<<<3 * KS, 256>>>(ln1 + l * D, qw + MO, D, D,      0, l, t);
            k_ln_gemv<<<3 * KS, 256>>>(ln1 + l * D, kw + MO, D, TT * D, 1, l, t);
            k_ln_gemv<<<3 * KS, 256>>>(ln1 + l * D, vw + MO, D, TT * D, 2, l, t);
            k_self_attn<<<NB * NH, 64>>>(rb, l, t);
            k_gemv_res<<<3 * 8, 256>>>(ow + MO, D, 96, 0);
            k_zero<<<30, 256>>>(1, l, t);
            k_ln_gemv<<<3 * KS, 256>>>(ln2 + l * D, cqw + MO, D, D, 0, l, t);
            k_cross_attn<<<NB * NH, 256>>>(l);
            k_gemv_res<<<3 * 8, 256>>>(cow + MO, D, 96, 0);
            k_ln_gemv<<<12 * KS, 256>>>(ln3 + l * D, wi + (size_t)l * D * DFF, DFF, DFF, 3, l, t);
            k_gemv_res<<<3 * 16, 256>>>(wo + (size_t)l * DFF * D, DFF, 192, 1);
        }
        k_final_rms<<<1, 256>>>(fln);
        k_logits<<<NV / 8, 256>>>(emb, out, t);
        if (t + 1 < TT) k_argmax<<<NB, 256>>>(out, t);
    }
}

// round 3
// speedup vs baseline: 1.7875x; 1.7875x over previous
#include <cuda_runtime.h>

#define D    768
#define NH   12
#define DKH  64
#define TT   16
#define ENCL 256
#define DFF  3072
#define NV   32128
#define NL   4
#define NB   2
#define EPSF 1e-6f
#define RSQRT_D 0.03608439182435161f   // 768^-0.5
#define NBLK 148
#define NTHR 256

// ------------------------------------------------------------------ scratch
__device__ float g_x  [NB*D];
__device__ float g_q  [NB*D];
__device__ float g_q2 [NB*D];
__device__ float g_att[NB*D];
__device__ float g_ff [NB*DFF];
__device__ float g_kc [NL*NB*TT*D];
__device__ float g_vc [NL*NB*TT*D];
__device__ float g_ckt[NL*NB*NH*DKH*ENCL];   // cross K transposed [l][b][h][dk][pos]
__device__ float g_cv [NL*NB*ENCL*D];        // cross V natural
__device__ unsigned long long g_amax[NB];
__device__ unsigned g_bar_count;
__device__ volatile unsigned g_bar_gen;

struct Params {
    const float *emb, *ln1, *qw, *kw, *vw, *ow, *ln2, *cqw, *cow, *ln3, *wi, *wo, *fln, *rb;
    float* out;
};

// ------------------------------------------------------------------ grid barrier
__device__ __forceinline__ void gsync() {
    __syncthreads();
    if (threadIdx.x == 0) {
        unsigned gen = g_bar_gen;
        __threadfence();
        if (atomicAdd(&g_bar_count, 1u) == NBLK - 1) {
            g_bar_count = 0;
            __threadfence();
            g_bar_gen = gen + 1;
        } else {
            while (g_bar_gen == gen) { }
            __threadfence();
        }
    }
    __syncthreads();
}

// ------------------------------------------------------------------ rms (redundant per block)
__device__ __forceinline__ float2 rms2(float* sred) {
    float s0 = 0.f, s1 = 0.f;
    for (int i = threadIdx.x; i < D; i += NTHR) {
        float a = __ldcg(&g_x[i]), b = __ldcg(&g_x[D + i]);
        s0 += a * a; s1 += b * b;
    }
    #pragma unroll
    for (int o = 16; o; o >>= 1) {
        s0 += __shfl_xor_sync(0xffffffffu, s0, o);
        s1 += __shfl_xor_sync(0xffffffffu, s1, o);
    }
    if ((threadIdx.x & 31) == 0) {
        sred[threadIdx.x >> 5]       = s0;
        sred[8 + (threadIdx.x >> 5)] = s1;
    }
    __syncthreads();
    if (threadIdx.x == 0) {
        float t0 = 0.f, t1 = 0.f;
        #pragma unroll
        for (int w = 0; w < 8; w++) { t0 += sred[w]; t1 += sred[8 + w]; }
        sred[16] = rsqrtf(t0 / (float)D + EPSF);
        sred[17] = rsqrtf(t1 / (float)D + EPSF);
    }
    __syncthreads();
    float2 r; r.x = sred[16]; r.y = sred[17];
    __syncthreads();
    return r;
}

__device__ __forceinline__ void gemv_ksplit(
    const float* __restrict__ W, int Dout,
    const float* sh0, const float* sh1, int i0, int klen,
    int tile, float* o0, float* o1)
{
    int col = (tile << 8) + threadIdx.x;
    const float* Wp = W + (size_t)i0 * Dout + col;
    float a0 = 0.f, a1 = 0.f;
    #pragma unroll 8
    for (int i = 0; i < klen; i++) {
        float w = Wp[(size_t)i * Dout];
        a0 += sh0[i] * w; a1 += sh1[i] * w;
    }
    atomicAdd(o0 + col, a0);
    atomicAdd(o1 + col, a1);
}

__device__ __forceinline__ void fill_norm(float* sh0, float* sh1,
    const float* lnw, int i0, int klen, float2 inv)
{
    if (threadIdx.x < klen) {
        int i = threadIdx.x;
        float w = lnw[i0 + i];
        sh0[i] = __ldcg(&g_x[i0 + i])     * inv.x * w;
        sh1[i] = __ldcg(&g_x[D + i0 + i]) * inv.y * w;
    }
    __syncthreads();
}

// ------------------------------------------------------------------ persistent decode kernel
__global__ __launch_bounds__(NTHR) void k_decode(Params p) {
    __shared__ float s[2048];
    float* sred = s;          // [18]
    float* sh0  = s + 32;     // [64]
    float* sh1  = s + 96;     // [64]
    const int bx = blockIdx.x, tid = threadIdx.x;

    // ---- init (re-run each graph replay for determinism)
    for (int i = bx * NTHR + tid; i < NL * NB * TT * D; i += NBLK * NTHR) {
        g_kc[i] = 0.f; g_vc[i] = 0.f;
    }
    for (int i = bx * NTHR + tid; i < NB * D; i += NBLK * NTHR) g_q[i] = 0.f;
    for (int i = bx * NTHR + tid; i < NB * DFF; i += NBLK * NTHR) g_ff[i] = 0.f;
    if (bx == 0 && tid < NB) g_amax[tid] = 0ull;
    gsync();

    for (int t = 0; t < TT; t++) {
        // ---- embed phase
        if (bx == 0) {
            __shared__ int stok[NB];
            if (tid < NB) {
                int tok = 0;
                if (t > 0) {
                    unsigned long long k = *((volatile unsigned long long*)&g_amax[tid]);
                    tok = NV - 1 - (int)(k & 0xffffffffull);
                }
                stok[tid] = tok;
            }
            __syncthreads();
            for (int i = tid; i < NB * D; i += NTHR) {
                int b = i / D, d = i % D;
                g_x[i] = p.emb[(size_t)stok[b] * D + d];
            }
        }
        gsync();

        for (int l = 0; l < NL; l++) {
            const size_t MO  = (size_t)l * D * D;
            const float* kcb = g_kc + ((size_t)(l * NB) * TT + t) * D;
            const float* vcb = g_vc + ((size_t)(l * NB) * TT + t) * D;

            // ---- phase: qkv gemv (144 jobs: 3 mats x 3 tiles x 16 splits, klen=48)
            if (bx < 144) {
                float2 inv = rms2(sred);
                int mat = bx / 48, r = bx % 48, tile = r / 16, ks = r % 16;
                int i0 = ks * 48;
                fill_norm(sh0, sh1, p.ln1 + l * D, i0, 48, inv);
                if (mat == 0)
                    gemv_ksplit(p.qw + MO, D, sh0, sh1, i0, 48, tile, g_q, g_q + D);
                else if (mat == 1)
                    gemv_ksplit(p.kw + MO, D, sh0, sh1, i0, 48, tile,
                                (float*)kcb, (float*)kcb + TT * D);
                else
                    gemv_ksplit(p.vw + MO, D, sh0, sh1, i0, 48, tile,
                                (float*)vcb, (float*)vcb + TT * D);
            } else if (bx == 147 && tid < NB) {
                g_amax[tid] = 0ull;   // reset for this step's logits argmax
            }
            gsync();

            // ---- phase: self-attn (24 jobs) + idle blocks zero g_q2, g_ff
            if (bx < 24) {
                int b = bx / NH, h = bx % NH;
                float* sq = s + 32; float* sp = s + 96; float* se = s + 112;
                if (tid < DKH) sq[tid] = __ldcg(&g_q[b * D + h * DKH + tid]);
                __syncthreads();
                int n = t + 1;
                if (tid < n) {
                    const float* kp = g_kc + ((size_t)(l * NB + b) * TT + tid) * D + h * DKH;
                    float sc = 0.f;
                    #pragma unroll
                    for (int d = 0; d < DKH; d++) sc += sq[d] * __ldcg(kp + d);
                    sp[tid] = sc + p.rb[(t - tid) * NH + h];
                }
                __syncthreads();
                if (tid < n) {
                    float mx = -1e30f;
                    for (int j = 0; j < n; j++) mx = fmaxf(mx, sp[j]);
                    se[tid] = expf(sp[tid] - mx);
                }
                __syncthreads();
                if (tid < DKH) {
                    float sum = 0.f, o = 0.f;
                    for (int j = 0; j < n; j++) {
                        sum += se[j];
                        o += se[j] * __ldcg(&g_vc[((size_t)(l * NB + b) * TT + j) * D + h * DKH + tid]);
                    }
                    g_att[b * D + h * DKH + tid] = o / sum;
                }
            } else {
                int idx = (bx - 24) * NTHR + tid;
                if (idx < NB * D) g_q2[idx] = 0.f;
                else if (idx < NB * D + NB * DFF) g_ff[idx - NB * D] = 0.f;
            }
            gsync();

            // ---- phase: o-proj + residual (144 jobs: 3 tiles x 48 splits, klen=16)
            if (bx < 144) {
                int tile = bx / 48, ks = bx % 48, i0 = ks * 16;
                if (tid < 16) {
                    sh0[tid] = __ldcg(&g_att[i0 + tid]);
                    sh1[tid] = __ldcg(&g_att[D + i0 + tid]);
                }
                __syncthreads();
                gemv_ksplit(p.ow + MO, D, sh0, sh1, i0, 16, tile, g_x, g_x + D);
            }
            gsync();

            // ---- phase: cq gemv (144 jobs, klen=16) into g_q2
            if (bx < 144) {
                float2 inv = rms2(sred);
                int tile = bx / 48, ks = bx % 48, i0 = ks * 16;
                fill_norm(sh0, sh1, p.ln2 + l * D, i0, 16, inv);
                gemv_ksplit(p.cqw + MO, D, sh0, sh1, i0, 16, tile, g_q2, g_q2 + D);
            }
            gsync();

            // ---- phase: cross-attn (24 jobs) + idle blocks zero g_q
            if (bx < 24) {
                int b = bx / NH, h = bx % NH;
                float* sq  = s + 32;   // 64
                float* se  = s + 96;   // 256
                float* red = s + 352;  // 8
                float* sMS = s + 360;  // 2
                float* so  = s + 368;  // 4*64
                if (tid < DKH) sq[tid] = __ldcg(&g_q2[b * D + h * DKH + tid]);
                __syncthreads();
                const float* kt = g_ckt + ((size_t)((l * NB + b) * NH + h) * DKH) * ENCL;
                float sc = 0.f;
                #pragma unroll 16
                for (int d = 0; d < DKH; d++) sc += sq[d] * kt[(size_t)d * ENCL + tid];
                float m = sc;
                for (int o = 16; o; o >>= 1) m = fmaxf(m, __shfl_xor_sync(0xffffffffu, m, o));
                if ((tid & 31) == 0) red[tid >> 5] = m;
                __syncthreads();
                if (tid == 0) {
                    float mm = red[0];
                    for (int w = 1; w < 8; w++) mm = fmaxf(mm, red[w]);
                    sMS[0] = mm;
                }
                __syncthreads();
                float e = expf(sc - sMS[0]);
                se[tid] = e;
                float ss = e;
                for (int o = 16; o; o >>= 1) ss += __shfl_xor_sync(0xffffffffu, ss, o);
                if ((tid & 31) == 0) red[tid >> 5] = ss;
                __syncthreads();
                if (tid == 0) {
                    float t2 = 0.f;
                    for (int w = 0; w < 8; w++) t2 += red[w];
                    sMS[1] = t2;
                }
                __syncthreads();
                int g = tid >> 6, d = tid & 63;
                const float* vp = g_cv + (size_t)((l * NB + b) * ENCL) * D + h * DKH + d;
                float acc = 0.f;
                for (int j = g * 64; j < g * 64 + 64; j++) acc += se[j] * vp[(size_t)j * D];
                so[g * 64 + d] = acc;
                __syncthreads();
                if (tid < DKH)
                    g_att[b * D + h * DKH + tid] =
                        (so[tid] + so[64 + tid] + so[128 + tid] + so[192 + tid]) / sMS[1];
            } else {
                int idx = (bx - 24) * NTHR + tid;
                if (idx < NB * D) g_q[idx] = 0.f;
            }
            gsync();

            // ---- phase: co-proj + residual
            if (bx < 144) {
                int tile = bx / 48, ks = bx % 48, i0 = ks * 16;
                if (tid < 16) {
                    sh0[tid] = __ldcg(&g_att[i0 + tid]);
                    sh1[tid] = __ldcg(&g_att[D + i0 + tid]);
                }
                __syncthreads();
                gemv_ksplit(p.cow + MO, D, sh0, sh1, i0, 16, tile, g_x, g_x + D);
            }
            gsync();

            // ---- phase: wi gemv (144 jobs: 12 tiles x 12 splits, klen=64)
            if (bx < 144) {
                float2 inv = rms2(sred);
                int tile = bx / 12, ks = bx % 12, i0 = ks * 64;
                fill_norm(sh0, sh1, p.ln3 + l * D, i0, 64, inv);
                gemv_ksplit(p.wi + (size_t)l * D * DFF, DFF, sh0, sh1, i0, 64, tile,
                            g_ff, g_ff + DFF);
            }
            gsync();

            // ---- phase: wo gemv + residual (144 jobs: 3 tiles x 48 splits, klen=64)
            if (bx < 144) {
                int tile = bx / 48, ks = bx % 48, i0 = ks * 64;
                if (tid < 64) {
                    sh0[tid] = fmaxf(__ldcg(&g_ff[i0 + tid]), 0.f);
                    sh1[tid] = fmaxf(__ldcg(&g_ff[DFF + i0 + tid]), 0.f);
                }
                __syncthreads();
                gemv_ksplit(p.wo + (size_t)l * DFF * D, D, sh0, sh1, i0, 64, tile,
                            g_x, g_x + D);
            }
            gsync();
        }

        // ---- phase: final rms + logits + fused argmax (all 148 blocks)
        {
            float2 inv = rms2(sred);
            float* sx0 = s + 32;    // 768
            float* sx1 = s + 800;   // 768
            for (int i = tid; i < D; i += NTHR) {
                float w = p.fln[i] * RSQRT_D;
                sx0[i] = __ldcg(&g_x[i])     * inv.x * w;
                sx1[i] = __ldcg(&g_x[D + i]) * inv.y * w;
            }
            __syncthreads();
            int warp = tid >> 5, lane = tid & 31;
            unsigned long long best0 = 0ull, best1 = 0ull;
            for (int v = bx * 8 + warp; v < NV; v += NBLK * 8) {
                const float4* e = (const float4*)(p.emb + (size_t)v * D);
                float a0 = 0.f, a1 = 0.f;
                #pragma unroll
                for (int i = lane; i < D / 4; i += 32) {
                    float4 w = e[i];
                    a0 += w.x * sx0[4*i] + w.y * sx0[4*i+1] + w.z * sx0[4*i+2] + w.w * sx0[4*i+3];
                    a1 += w.x * sx1[4*i] + w.y * sx1[4*i+1] + w.z * sx1[4*i+2] + w.w * sx1[4*i+3];
                }
                for (int o = 16; o; o >>= 1) {
                    a0 += __shfl_xor_sync(0xffffffffu, a0, o);
                    a1 += __shfl_xor_sync(0xffffffffu, a1, o);
                }
                if (lane == 0) {
                    p.out[((size_t)0 * TT + t) * NV + v] = a0;
                    p.out[((size_t)1 * TT + t) * NV + v] = a1;
                    unsigned b0 = __float_as_uint(a0);
                    unsigned b1 = __float_as_uint(a1);
                    unsigned u0 = (b0 & 0x80000000u) ? ~b0 : (b0 | 0x80000000u);
                    unsigned u1 = (b1 & 0x80000000u) ? ~b1 : (b1 | 0x80000000u);
                    unsigned long long k0 = ((unsigned long long)u0 << 32) | (unsigned)(NV - 1 - v);
                    unsigned long long k1 = ((unsigned long long)u1 << 32) | (unsigned)(NV - 1 - v);
                    if (k0 > best0) best0 = k0;
                    if (k1 > best1) best1 = k1;
                }
            }
            if (lane == 0) {
                atomicMax(&g_amax[0], best0);
                atomicMax(&g_amax[1], best1);
            }
        }
        gsync();
    }
}

// ------------------------------------------------------------------ cross K/V precompute
__global__ __launch_bounds__(256) void k_cross_kv(
    const float* __restrict__ enc, const float* __restrict__ ckw,
    const float* __restrict__ cvw)
{
    __shared__ float sx[8][D];
    int bx = blockIdx.x;
    int c   = bx % 3; bx /= 3;
    int rb  = bx % 64; bx /= 64;
    int mat = bx % 2;
    int l   = bx / 2;
    int row0 = rb * 8;
    for (int i = threadIdx.x; i < 8 * D; i += 256)
        sx[i / D][i % D] = enc[(size_t)row0 * D + i];
    __syncthreads();
    const float* W = (mat == 0 ? ckw : cvw) + (size_t)l * D * D;
    int col = c * 256 + threadIdx.x;
    float acc[8];
    #pragma unroll
    for (int r = 0; r < 8; r++) acc[r] = 0.f;
    const float* Wp = W + col;
    #pragma unroll 4
    for (int i = 0; i < D; i++) {
        float w = Wp[(size_t)i * D];
        #pragma unroll
        for (int r = 0; r < 8; r++) acc[r] += sx[r][i] * w;
    }
    int h = col / DKH, dd = col % DKH;
    for (int r = 0; r < 8; r++) {
        int g = row0 + r; int b = g / ENCL; int pnum = g % ENCL;
        if (mat == 0)
            g_ckt[(((size_t)(l * NB + b) * NH + h) * DKH + dd) * ENCL + pnum] = acc[r];
        else
            g_cv[((size_t)(l * NB + b) * ENCL + pnum) * D + col] = acc[r];
    }
}

// ------------------------------------------------------------------ launch
extern "C" void kernel_launch(void* const* d_in, const int* in_sizes, int n_in,
                              void* d_out, int out_size) {
    Params p;
    const float* enc = (const float*)d_in[0];
    p.emb = (const float*)d_in[1];
    p.ln1 = (const float*)d_in[2];
    p.qw  = (const float*)d_in[3];
    p.kw  = (const float*)d_in[4];
    p.vw  = (const float*)d_in[5];
    p.ow  = (const float*)d_in[6];
    p.ln2 = (const float*)d_in[7];
    p.cqw = (const float*)d_in[8];
    const float* ckw = (const float*)d_in[9];
    const float* cvw = (const float*)d_in[10];
    p.cow = (const float*)d_in[11];
    p.ln3 = (const float*)d_in[12];
    p.wi  = (const float*)d_in[13];
    p.wo  = (const float*)d_in[14];
    p.fln = (const float*)d_in[15];
    p.rb  = (const float*)d_in[16];
    p.out = (float*)d_out;

    k_cross_kv<<<1536, 256>>>(enc, ckw, cvw);
    k_decode<<<NBLK, NTHR>>>(p);
}